// round 1
// baseline (speedup 1.0000x reference)
#include <cuda_runtime.h>

// ChessMultiStageAttention — persistent-CTA fused fp32 baseline.
// One CTA processes batches pulled from a global work counter; all per-batch
// tensors live in shared memory with bank-conflict-free padded layouts.

#define TPB 256
#define NBATCH 4096

__device__ int g_next_batch;

__global__ void hx_reset_counter() { g_next_batch = 0; }

extern "C" __global__ void __launch_bounds__(TPB)
chess_attn_kernel(const float* __restrict__ gx,
                  const float* __restrict__ gpos,
                  const float* __restrict__ ggamma,
                  const float* __restrict__ gbeta,
                  const float* __restrict__ gqkvw,   // [192,64]
                  const float* __restrict__ gqkvb,   // [192]
                  const float* __restrict__ goutw,   // [64,64]
                  const float* __restrict__ goutb,   // [64]
                  const float* __restrict__ gcb,     // [64,64]
                  float* __restrict__ gout)
{
    extern __shared__ float sm[];
    // layout (floats); qkv/wT first for 16B alignment of float4 accesses
    float* sm_qkv = sm;                  // 64*196 = 12544
    float* sm_wT  = sm_qkv + 12544;      // 64*196 = 12544  wT[e][j] = qkv_w[j][e]
    float* sm_xT  = sm_wT  + 12544;      // 64*65  = 4160   xT[s][e] = x+pos (also residual)
    float* sm_xn  = sm_xT  + 4160;       // 4160           normed x; reused as ybuf
    float* sm_ao  = sm_xn  + 4160;       // 4160           attention out [s][e]
    float* sm_cb  = sm_ao  + 4160;       // 4160           chess bias [s][t] padded
    float* sm_owT = sm_cb  + 4160;       // 4160           owT[t][e] = out_w[e][t]
    float* sm_pos = sm_owT + 4160;       // 4096
    float* sm_qb  = sm_pos + 4096;       // 192
    float* sm_ob  = sm_qb  + 192;        // 64
    float* sm_g   = sm_ob  + 64;         // 64
    float* sm_bt  = sm_g   + 64;         // 64
    int*   sm_bb  = (int*)(sm_bt + 64);  // 1 (batch broadcast)

    const int tid  = threadIdx.x;
    const int lane = tid & 31;
    const int warp = tid >> 5;
    const int tx   = tid & 15;
    const int ty   = tid >> 4;

    // ---- stage constants (once per CTA) ----
    for (int i = tid; i < 192 * 64; i += TPB) {
        int j = i >> 6, e = i & 63;
        sm_wT[e * 196 + j] = gqkvw[i];
    }
    for (int i = tid; i < 64 * 64; i += TPB) {
        int e = i >> 6, t = i & 63;
        sm_owT[t * 65 + e] = goutw[i];
    }
    for (int i = tid; i < 64 * 64; i += TPB) {
        int s = i >> 6, t = i & 63;
        sm_cb[s * 65 + t] = gcb[i];
    }
    for (int i = tid; i < 4096; i += TPB) sm_pos[i] = gpos[i];
    if (tid < 192) sm_qb[tid] = gqkvb[tid];
    if (tid < 64) { sm_ob[tid] = goutb[tid]; sm_g[tid] = ggamma[tid]; sm_bt[tid] = gbeta[tid]; }

    while (true) {
        __syncthreads();                       // protects smem reuse + bcast slot
        if (tid == 0) sm_bb[0] = atomicAdd(&g_next_batch, 1);
        __syncthreads();
        int b = sm_bb[0];
        if (b >= NBATCH) break;
        const float* xb = gx + (size_t)b * 4096;

        // ---- phase 1: load + pos-embed, transpose to [s][e] ----
        for (int i = tid; i < 4096; i += TPB) {
            int e = i >> 6, s = i & 63;
            sm_xT[s * 65 + e] = xb[i] + sm_pos[i];
        }
        __syncthreads();

        // ---- phase 2: LayerNorm over e (warp per row) ----
        for (int it = 0; it < 8; it++) {
            int s = it * 8 + warp;
            float v0 = sm_xT[s * 65 + lane];
            float v1 = sm_xT[s * 65 + 32 + lane];
            float sum = v0 + v1;
            float sq  = v0 * v0 + v1 * v1;
            #pragma unroll
            for (int off = 16; off; off >>= 1) {
                sum += __shfl_xor_sync(0xffffffffu, sum, off);
                sq  += __shfl_xor_sync(0xffffffffu, sq,  off);
            }
            float mu  = sum * (1.0f / 64.0f);
            float var = sq  * (1.0f / 64.0f) - mu * mu;
            float rs  = rsqrtf(var + 1e-5f);
            sm_xn[s * 65 + lane]      = (v0 - mu) * rs * sm_g[lane]      + sm_bt[lane];
            sm_xn[s * 65 + 32 + lane] = (v1 - mu) * rs * sm_g[lane + 32] + sm_bt[lane + 32];
        }
        __syncthreads();

        // ---- phase 3: QKV GEMM  qkv[s][j] = xn[s][:] . wT[:][j] + qb[j] ----
        {
            float acc[4][12];
            #pragma unroll
            for (int ss = 0; ss < 4; ss++)
                #pragma unroll
                for (int jj = 0; jj < 12; jj++) acc[ss][jj] = 0.f;
            #pragma unroll 4
            for (int e = 0; e < 64; e++) {
                float a[4], w[12];
                #pragma unroll
                for (int ss = 0; ss < 4; ss++) a[ss] = sm_xn[(ty + 16 * ss) * 65 + e];
                #pragma unroll
                for (int jj = 0; jj < 12; jj++) w[jj] = sm_wT[e * 196 + tx + 16 * jj];
                #pragma unroll
                for (int ss = 0; ss < 4; ss++)
                    #pragma unroll
                    for (int jj = 0; jj < 12; jj++)
                        acc[ss][jj] += a[ss] * w[jj];
            }
            #pragma unroll
            for (int ss = 0; ss < 4; ss++)
                #pragma unroll
                for (int jj = 0; jj < 12; jj++)
                    sm_qkv[(ty + 16 * ss) * 196 + tx + 16 * jj] = acc[ss][jj] + sm_qb[tx + 16 * jj];
        }
        __syncthreads();

        // ---- phase 4: attention (thread = one (head,row); warp shares head) ----
        #pragma unroll 1
        for (int iter = 0; iter < 2; iter++) {
            int row = iter * TPB + tid;        // 0..511
            int h = row >> 6, s = row & 63;
            const float* qp = sm_qkv + s * 196 + h * 8;
            float4 q0 = *(const float4*)qp;
            float4 q1 = *(const float4*)(qp + 4);
            float sc[64];
            float mx = -1e30f;
            #pragma unroll
            for (int t = 0; t < 64; t++) {
                const float* kp = sm_qkv + t * 196 + 64 + h * 8;
                float4 k0 = *(const float4*)kp;
                float4 k1 = *(const float4*)(kp + 4);
                float d = q0.x * k0.x + q0.y * k0.y + q0.z * k0.z + q0.w * k0.w
                        + q1.x * k1.x + q1.y * k1.y + q1.z * k1.z + q1.w * k1.w;
                d = d * 0.35355339059327373f + sm_cb[s * 65 + t];
                sc[t] = d;
                mx = fmaxf(mx, d);
            }
            float sum = 0.f;
            #pragma unroll
            for (int t = 0; t < 64; t++) {
                float ev = __expf(sc[t] - mx);
                sc[t] = ev;
                sum += ev;
            }
            float inv = 1.0f / sum;
            float acc[8];
            #pragma unroll
            for (int d = 0; d < 8; d++) acc[d] = 0.f;
            #pragma unroll
            for (int t = 0; t < 64; t++) {
                const float* vp = sm_qkv + t * 196 + 128 + h * 8;
                float4 v0 = *(const float4*)vp;
                float4 v1 = *(const float4*)(vp + 4);
                float p = sc[t];
                acc[0] += p * v0.x; acc[1] += p * v0.y;
                acc[2] += p * v0.z; acc[3] += p * v0.w;
                acc[4] += p * v1.x; acc[5] += p * v1.y;
                acc[6] += p * v1.z; acc[7] += p * v1.w;
            }
            #pragma unroll
            for (int d = 0; d < 8; d++)
                sm_ao[s * 65 + h * 8 + d] = acc[d] * inv;
        }
        __syncthreads();

        // ---- phase 5: out-proj  y[s][e] = ao[s][:] . owT[:][e] + ob[e]  (into sm_xn) ----
        {
            float acc[4][4];
            #pragma unroll
            for (int ss = 0; ss < 4; ss++)
                #pragma unroll
                for (int ee = 0; ee < 4; ee++) acc[ss][ee] = 0.f;
            #pragma unroll 4
            for (int t = 0; t < 64; t++) {
                float a[4], w[4];
                #pragma unroll
                for (int ss = 0; ss < 4; ss++) a[ss] = sm_ao[(ty + 16 * ss) * 65 + t];
                #pragma unroll
                for (int ee = 0; ee < 4; ee++) w[ee] = sm_owT[t * 65 + tx + 16 * ee];
                #pragma unroll
                for (int ss = 0; ss < 4; ss++)
                    #pragma unroll
                    for (int ee = 0; ee < 4; ee++) acc[ss][ee] += a[ss] * w[ee];
            }
            #pragma unroll
            for (int ss = 0; ss < 4; ss++)
                #pragma unroll
                for (int ee = 0; ee < 4; ee++)
                    sm_xn[(ty + 16 * ss) * 65 + tx + 16 * ee] = acc[ss][ee] + sm_ob[tx + 16 * ee];
        }
        __syncthreads();

        // ---- phase 6: residual + transpose back, coalesced store ----
        float* ob = gout + (size_t)b * 4096;
        for (int i = tid; i < 4096; i += TPB) {
            int e = i >> 6, s = i & 63;
            ob[i] = sm_xT[s * 65 + e] + sm_xn[s * 65 + e];
        }
    }
}

static const int SMEM_FLOATS = 12544 + 12544 + 4160 * 5 + 4096 + 192 + 64 * 3;
static const int SMEM_BYTES  = SMEM_FLOATS * 4 + 16;   // + int bcast slot / pad

extern "C" void kernel_launch(void* const* d_in, const int* in_sizes, int n_in,
                              void* d_out, int out_size)
{
    (void)in_sizes; (void)n_in; (void)out_size;
    cudaFuncSetAttribute(chess_attn_kernel,
                         cudaFuncAttributeMaxDynamicSharedMemorySize, SMEM_BYTES);
    hx_reset_counter<<<1, 1>>>();
    chess_attn_kernel<<<152, TPB, SMEM_BYTES>>>(
        (const float*)d_in[0],   // x
        (const float*)d_in[1],   // pos_embed
        (const float*)d_in[2],   // ln_gamma
        (const float*)d_in[3],   // ln_beta
        (const float*)d_in[4],   // qkv_w
        (const float*)d_in[5],   // qkv_b
        (const float*)d_in[6],   // out_w
        (const float*)d_in[7],   // out_b
        (const float*)d_in[8],   // chess_bias
        (float*)d_out);
}

// round 2
// speedup vs baseline: 1.0481x; 1.0481x over previous
#include <cuda_runtime.h>

// ChessMultiStageAttention — persistent-CTA fused fp32, f32x2-packed math.
// Round 2: FFMA2 (fma.rn.f32x2) in all GEMM/attention inner loops, fused
// single-pass softmax (no max-subtract, exp2-based), pair-packed smem weights.

#define TPB 256
#define NBATCH 4096
typedef unsigned long long ull;

__device__ int g_next_batch;
__global__ void hx_reset_counter() { g_next_batch = 0; }

__device__ __forceinline__ ull pk2(float x, float y) {
    ull r; asm("mov.b64 %0,{%1,%2};" : "=l"(r) : "f"(x), "f"(y)); return r;
}
__device__ __forceinline__ void up2(ull p, float& x, float& y) {
    asm("mov.b64 {%0,%1},%2;" : "=f"(x), "=f"(y) : "l"(p));
}
__device__ __forceinline__ ull fma2_(ull a, ull b, ull c) {
    ull d; asm("fma.rn.f32x2 %0,%1,%2,%3;" : "=l"(d) : "l"(a), "l"(b), "l"(c)); return d;
}
__device__ __forceinline__ ull mul2_(ull a, ull b) {
    ull d; asm("mul.rn.f32x2 %0,%1,%2;" : "=l"(d) : "l"(a), "l"(b)); return d;
}
__device__ __forceinline__ float ex2_(float x) {
    float r; asm("ex2.approx.f32 %0,%1;" : "=f"(r) : "f"(x)); return r;
}

#define LOG2E 1.4426950408889634f
#define KSCALE (0.35355339059327373f * 1.4426950408889634f)

extern "C" __global__ void __launch_bounds__(TPB)
chess_attn_kernel(const float* __restrict__ gx,
                  const float* __restrict__ gpos,
                  const float* __restrict__ ggamma,
                  const float* __restrict__ gbeta,
                  const float* __restrict__ gqkvw,   // [192,64]
                  const float* __restrict__ gqkvb,   // [192]
                  const float* __restrict__ goutw,   // [64,64]
                  const float* __restrict__ goutb,   // [64]
                  const float* __restrict__ gcb,     // [64,64]
                  float* __restrict__ gout)
{
    extern __shared__ float sm[];
    float* sm_qkv = sm;                  // 64*196 = 12544 (qkv, later y-buffer)
    float* sm_w2f = sm_qkv + 12544;      // 64*192 = 12288  w2f[e][j] = qkv_w[j][e]
    float* sm_xT  = sm_w2f + 12288;      // 64*65  = 4160   x+pos, [s][e] (residual)
    float* sm_xn  = sm_xT  + 4160;       // 4160           LN output
    float* sm_ao  = sm_xn  + 4160;       // 64*66  = 4224   attention out [s][e]
    float* sm_cb  = sm_ao  + 4224;       // 64*65  = 4160   chess bias * log2e
    float* sm_owf = sm_cb  + 4160;       // 64*64  = 4096   owf[t][e] = out_w[e][t]
    float* sm_pos = sm_owf + 4096;       // 4096
    float* sm_qb  = sm_pos + 4096;       // 192
    float* sm_ob  = sm_qb  + 192;        // 64
    float* sm_g   = sm_ob  + 64;         // 64
    float* sm_bt  = sm_g   + 64;         // 64
    int*   sm_bb  = (int*)(sm_bt + 64);

    ull* qkvU = (ull*)sm_qkv;            // row stride 98
    ull* w2U  = (ull*)sm_w2f;            // row stride 96
    ull* aoU  = (ull*)sm_ao;             // row stride 33
    ull* owU  = (ull*)sm_owf;            // row stride 32
    ull* qbU  = (ull*)sm_qb;
    ull* obU  = (ull*)sm_ob;

    const int tid  = threadIdx.x;
    const int lane = tid & 31;
    const int warp = tid >> 5;
    const int tx   = tid & 15;
    const int ty   = tid >> 4;

    // ---- stage constants ----
    for (int i = tid; i < 192 * 64; i += TPB) {
        int j = i >> 6, e = i & 63;
        sm_w2f[e * 192 + j] = gqkvw[i];
    }
    for (int i = tid; i < 64 * 64; i += TPB) {
        int e = i >> 6, t = i & 63;
        sm_owf[t * 64 + e] = goutw[i];
    }
    for (int i = tid; i < 64 * 64; i += TPB) {
        int s = i >> 6, t = i & 63;
        sm_cb[s * 65 + t] = gcb[i] * LOG2E;
    }
    for (int i = tid; i < 4096; i += TPB) sm_pos[i] = gpos[i];
    if (tid < 192) sm_qb[tid] = gqkvb[tid];
    if (tid < 64) { sm_ob[tid] = goutb[tid]; sm_g[tid] = ggamma[tid]; sm_bt[tid] = gbeta[tid]; }

    while (true) {
        __syncthreads();
        if (tid == 0) sm_bb[0] = atomicAdd(&g_next_batch, 1);
        __syncthreads();
        int b = sm_bb[0];
        if (b >= NBATCH) break;
        const float4* xb4  = (const float4*)(gx + (size_t)b * 4096);
        const float4* pos4 = (const float4*)sm_pos;

        // ---- phase 1: load + pos, transpose to [s][e] ----
        for (int i4 = tid; i4 < 1024; i4 += TPB) {
            float4 xv = xb4[i4], pv = pos4[i4];
            int e = i4 >> 4, s0 = (i4 & 15) * 4;
            sm_xT[(s0 + 0) * 65 + e] = xv.x + pv.x;
            sm_xT[(s0 + 1) * 65 + e] = xv.y + pv.y;
            sm_xT[(s0 + 2) * 65 + e] = xv.z + pv.z;
            sm_xT[(s0 + 3) * 65 + e] = xv.w + pv.w;
        }
        __syncthreads();

        // ---- phase 2: LayerNorm (warp per row) ----
        for (int it = 0; it < 8; it++) {
            int s = it * 8 + warp;
            float v0 = sm_xT[s * 65 + lane];
            float v1 = sm_xT[s * 65 + 32 + lane];
            float sum = v0 + v1;
            float sq  = v0 * v0 + v1 * v1;
            #pragma unroll
            for (int off = 16; off; off >>= 1) {
                sum += __shfl_xor_sync(0xffffffffu, sum, off);
                sq  += __shfl_xor_sync(0xffffffffu, sq,  off);
            }
            float mu  = sum * (1.0f / 64.0f);
            float var = sq  * (1.0f / 64.0f) - mu * mu;
            float rs  = rsqrtf(var + 1e-5f);
            sm_xn[s * 65 + lane]      = (v0 - mu) * rs * sm_g[lane]      + sm_bt[lane];
            sm_xn[s * 65 + 32 + lane] = (v1 - mu) * rs * sm_g[lane + 32] + sm_bt[lane + 32];
        }
        __syncthreads();

        // ---- phase 3: QKV GEMM (packed f32x2, 4x6 x2-wide tile/thread) ----
        {
            ull acc[4][6];
            #pragma unroll
            for (int jj = 0; jj < 6; jj++) {
                ull bv = qbU[tx + 16 * jj];
                #pragma unroll
                for (int ss = 0; ss < 4; ss++) acc[ss][jj] = bv;
            }
            #pragma unroll 4
            for (int e = 0; e < 64; e++) {
                ull ap[4], w[6];
                #pragma unroll
                for (int ss = 0; ss < 4; ss++) {
                    float a = sm_xn[(ty + 16 * ss) * 65 + e];
                    ap[ss] = pk2(a, a);
                }
                #pragma unroll
                for (int jj = 0; jj < 6; jj++) w[jj] = w2U[e * 96 + tx + 16 * jj];
                #pragma unroll
                for (int ss = 0; ss < 4; ss++)
                    #pragma unroll
                    for (int jj = 0; jj < 6; jj++)
                        acc[ss][jj] = fma2_(ap[ss], w[jj], acc[ss][jj]);
            }
            #pragma unroll
            for (int ss = 0; ss < 4; ss++)
                #pragma unroll
                for (int jj = 0; jj < 6; jj++)
                    qkvU[(ty + 16 * ss) * 98 + tx + 16 * jj] = acc[ss][jj];
        }
        __syncthreads();

        // ---- phase 4: attention, fused single-pass softmax (exp2, no max) ----
        #pragma unroll 1
        for (int iter = 0; iter < 2; iter++) {
            int row = iter * TPB + tid;
            int h = row >> 6, s = row & 63;
            const ull* qr = qkvU + s * 98 + h * 4;
            ull q0 = qr[0], q1 = qr[1], q2 = qr[2], q3 = qr[3];
            const float* cbp = sm_cb + s * 65;
            float sums[4] = {0.f, 0.f, 0.f, 0.f};
            ull a0 = 0, a1 = 0, a2 = 0, a3 = 0;
            #pragma unroll
            for (int t = 0; t < 64; t++) {
                const ull* kr = qkvU + t * 98 + 32 + h * 4;
                ull d2 = mul2_(q0, kr[0]);
                d2 = fma2_(q1, kr[1], d2);
                d2 = fma2_(q2, kr[2], d2);
                d2 = fma2_(q3, kr[3], d2);
                float dl, dh; up2(d2, dl, dh);
                float p = ex2_(fmaf(dl + dh, KSCALE, cbp[t]));
                sums[t & 3] += p;
                ull pp = pk2(p, p);
                const ull* vr = qkvU + t * 98 + 64 + h * 4;
                a0 = fma2_(pp, vr[0], a0);
                a1 = fma2_(pp, vr[1], a1);
                a2 = fma2_(pp, vr[2], a2);
                a3 = fma2_(pp, vr[3], a3);
            }
            float inv = 1.0f / ((sums[0] + sums[1]) + (sums[2] + sums[3]));
            ull iv = pk2(inv, inv);
            ull* aor = aoU + s * 33 + h * 4;
            aor[0] = mul2_(a0, iv);
            aor[1] = mul2_(a1, iv);
            aor[2] = mul2_(a2, iv);
            aor[3] = mul2_(a3, iv);
        }
        __syncthreads();

        // ---- phase 5: out-proj (packed), y into sm_qkv buffer ----
        {
            ull acc[4][2];
            ull b0 = obU[tx], b1 = obU[tx + 16];
            #pragma unroll
            for (int ss = 0; ss < 4; ss++) { acc[ss][0] = b0; acc[ss][1] = b1; }
            #pragma unroll 4
            for (int t = 0; t < 64; t++) {
                ull ap[4];
                #pragma unroll
                for (int ss = 0; ss < 4; ss++) {
                    float a = sm_ao[(ty + 16 * ss) * 66 + t];
                    ap[ss] = pk2(a, a);
                }
                ull w0 = owU[t * 32 + tx], w1 = owU[t * 32 + tx + 16];
                #pragma unroll
                for (int ss = 0; ss < 4; ss++) {
                    acc[ss][0] = fma2_(ap[ss], w0, acc[ss][0]);
                    acc[ss][1] = fma2_(ap[ss], w1, acc[ss][1]);
                }
            }
            #pragma unroll
            for (int ss = 0; ss < 4; ss++) {
                qkvU[(ty + 16 * ss) * 98 + tx]      = acc[ss][0];
                qkvU[(ty + 16 * ss) * 98 + tx + 16] = acc[ss][1];
            }
        }
        __syncthreads();

        // ---- phase 6: residual + transpose back, float4 stores ----
        float4* ob4 = (float4*)(gout + (size_t)b * 4096);
        for (int i4 = tid; i4 < 1024; i4 += TPB) {
            int e = i4 >> 4, s0 = (i4 & 15) * 4;
            float4 o;
            o.x = sm_xT[(s0 + 0) * 65 + e] + sm_qkv[(s0 + 0) * 196 + e];
            o.y = sm_xT[(s0 + 1) * 65 + e] + sm_qkv[(s0 + 1) * 196 + e];
            o.z = sm_xT[(s0 + 2) * 65 + e] + sm_qkv[(s0 + 2) * 196 + e];
            o.w = sm_xT[(s0 + 3) * 65 + e] + sm_qkv[(s0 + 3) * 196 + e];
            ob4[i4] = o;
        }
    }
}

static const int SMEM_FLOATS = 12544 + 12288 + 4160 + 4160 + 4224 + 4160 + 4096 + 4096
                             + 192 + 64 + 64 + 64;
static const int SMEM_BYTES  = SMEM_FLOATS * 4 + 16;

extern "C" void kernel_launch(void* const* d_in, const int* in_sizes, int n_in,
                              void* d_out, int out_size)
{
    (void)in_sizes; (void)n_in; (void)out_size;
    cudaFuncSetAttribute(chess_attn_kernel,
                         cudaFuncAttributeMaxDynamicSharedMemorySize, SMEM_BYTES);
    hx_reset_counter<<<1, 1>>>();
    chess_attn_kernel<<<152, TPB, SMEM_BYTES>>>(
        (const float*)d_in[0], (const float*)d_in[1], (const float*)d_in[2],
        (const float*)d_in[3], (const float*)d_in[4], (const float*)d_in[5],
        (const float*)d_in[6], (const float*)d_in[7], (const float*)d_in[8],
        (float*)d_out);
}